// round 8
// baseline (speedup 1.0000x reference)
#include <cuda_runtime.h>
#include <cuda_bf16.h>

#define NPTS 2048
#define TPB  256
#define TILES (NPTS / TPB)   // 8
#define KNN  16
#define NB   8
#define G    8
#define NGROUPS (NPTS / G)     // 256 groups of 8
#define NSUPER  (NPTS / 32)    // 64 supergroups of 32
#define STPB 1024
#define NBLOCKS (TILES * NB * 2)   // 128

__device__ float g_part[2 * NB * TILES];
__device__ float4 g_sorted[2 * NB * NPTS];
__device__ float4 g_b8lo[2 * NB * NGROUPS];
__device__ float4 g_b8hi[2 * NB * NGROUPS];
__device__ float4 g_b32lo[2 * NB * NSUPER];
__device__ float4 g_b32hi[2 * NB * NSUPER];
__device__ unsigned g_cnt;

#define CE(a, b) { float _lo = fminf(a, b); float _hi = fmaxf(a, b); a = _lo; b = _hi; }

__device__ __forceinline__ unsigned expand3(unsigned v) {
    v &= 0x3FFu;
    v = (v | (v << 16)) & 0x030000FFu;
    v = (v | (v << 8))  & 0x0300F00Fu;
    v = (v | (v << 4))  & 0x030C30C3u;
    v = (v | (v << 2))  & 0x09249249u;
    return v;
}

// squared distance from point to AABB (true lower bound for any point inside)
__device__ __forceinline__ float box_lb(float px, float py, float pz,
                                        float4 lo, float4 hi) {
    const float dx = fmaxf(fmaxf(lo.x - px, px - hi.x), 0.0f);
    const float dy = fmaxf(fmaxf(lo.y - py, py - hi.y), 0.0f);
    const float dz = fmaxf(fmaxf(lo.z - pz, pz - hi.z), 0.0f);
    return fmaf(dx, dx, fmaf(dy, dy, dz * dz));
}

__global__ void __launch_bounds__(STPB, 1)
sort_kernel(const float* __restrict__ seed, const float* __restrict__ gt)
{
    __shared__ unsigned keys[NPTS];   // 8 KB
    __shared__ float4 spts[NPTS];     // 32 KB

    const int b = blockIdx.x;
    const int z = blockIdx.y;
    const float* pts = (z == 0 ? seed : gt) + (size_t)b * NPTS * 3;
    const int tid = threadIdx.x;

#pragma unroll
    for (int j = tid; j < NPTS; j += STPB) {
        const float x  = pts[3 * j + 0];
        const float y  = pts[3 * j + 1];
        const float zc = pts[3 * j + 2];
        spts[j] = make_float4(x, y, zc, fmaf(x, x, fmaf(y, y, zc * zc)));
        const unsigned qx = (unsigned)fminf(fmaxf((x  + 4.0f) * 16.0f, 0.0f), 127.0f);
        const unsigned qy = (unsigned)fminf(fmaxf((y  + 4.0f) * 16.0f, 0.0f), 127.0f);
        const unsigned qz = (unsigned)fminf(fmaxf((zc + 4.0f) * 16.0f, 0.0f), 127.0f);
        const unsigned code = (expand3(qx) << 2) | (expand3(qy) << 1) | expand3(qz);
        keys[j] = (code << 11) | (unsigned)j;   // unique -> deterministic
    }
    __syncthreads();

    // Bitonic sort, one compare-exchange per thread per phase
    for (unsigned k = 2; k <= NPTS; k <<= 1) {
        for (unsigned jj = k >> 1; jj > 0; jj >>= 1) {
            const unsigned t = (unsigned)tid;
            const unsigned i = ((t & ~(jj - 1u)) << 1) | (t & (jj - 1u));
            const unsigned pp = i | jj;
            const bool up = ((i & k) == 0u);
            const unsigned a  = keys[i];
            const unsigned c  = keys[pp];
            const unsigned lo = a < c ? a : c;
            const unsigned hi = a < c ? c : a;
            keys[i]  = up ? lo : hi;
            keys[pp] = up ? hi : lo;
            __syncthreads();
        }
    }

    const size_t base = (size_t)(z * NB + b);
    float4* dst = g_sorted + base * NPTS;
#pragma unroll
    for (int idx = tid; idx < NPTS; idx += STPB)
        dst[idx] = spts[keys[idx] & 2047u];

    // Per-group-of-8 AABBs over the SORTED order
    if (tid < NGROUPS) {
        float4 lo = make_float4( 3.4e38f,  3.4e38f,  3.4e38f, 0.f);
        float4 hi = make_float4(-3.4e38f, -3.4e38f, -3.4e38f, 0.f);
#pragma unroll
        for (int u = 0; u < 8; u++) {
            const float4 q = spts[keys[tid * 8 + u] & 2047u];
            lo.x = fminf(lo.x, q.x); lo.y = fminf(lo.y, q.y); lo.z = fminf(lo.z, q.z);
            hi.x = fmaxf(hi.x, q.x); hi.y = fmaxf(hi.y, q.y); hi.z = fmaxf(hi.z, q.z);
        }
        g_b8lo[base * NGROUPS + tid] = lo;
        g_b8hi[base * NGROUPS + tid] = hi;
    }
    __syncthreads();   // global writes by block visible to block after this

    if (tid < NSUPER) {
        float4 lo = make_float4( 3.4e38f,  3.4e38f,  3.4e38f, 0.f);
        float4 hi = make_float4(-3.4e38f, -3.4e38f, -3.4e38f, 0.f);
#pragma unroll
        for (int u = 0; u < 4; u++) {
            const float4 l = g_b8lo[base * NGROUPS + tid * 4 + u];
            const float4 h = g_b8hi[base * NGROUPS + tid * 4 + u];
            lo.x = fminf(lo.x, l.x); lo.y = fminf(lo.y, l.y); lo.z = fminf(lo.z, l.z);
            hi.x = fmaxf(hi.x, h.x); hi.y = fmaxf(hi.y, h.y); hi.z = fmaxf(hi.z, h.z);
        }
        g_b32lo[base * NSUPER + tid] = lo;
        g_b32hi[base * NSUPER + tid] = hi;
    }
}

__global__ void __launch_bounds__(TPB, 1)
knn_kernel(float* __restrict__ out)
{
    __shared__ float4 sm[NPTS];            // 32 KB
    __shared__ float4 b8lo[NGROUPS];       // 4 KB
    __shared__ float4 b8hi[NGROUPS];       // 4 KB
    __shared__ float4 b32lo[NSUPER];       // 1 KB
    __shared__ float4 b32hi[NSUPER];       // 1 KB
    __shared__ float warp_sums[TPB / 32];
    __shared__ unsigned s_ticket;

    const int tile = blockIdx.x;
    const int b    = blockIdx.y;
    const int z    = blockIdx.z;
    const size_t bb = (size_t)(z * NB + b);

    const float4* src = g_sorted + bb * NPTS;
    for (int j = threadIdx.x; j < NPTS; j += TPB)
        sm[j] = src[j];
    for (int j = threadIdx.x; j < NGROUPS; j += TPB) {
        b8lo[j] = g_b8lo[bb * NGROUPS + j];
        b8hi[j] = g_b8hi[bb * NGROUPS + j];
    }
    if (threadIdx.x < NSUPER) {
        b32lo[threadIdx.x] = g_b32lo[bb * NSUPER + threadIdx.x];
        b32hi[threadIdx.x] = g_b32hi[bb * NSUPER + threadIdx.x];
    }
    __syncthreads();

    const int i = tile * TPB + threadIdx.x;
    const float4 p = sm[i];
    const float px = p.x, py = p.y, pz = p.z;
    const float si  = p.w;
    const float m2x = -2.0f * px;
    const float m2y = -2.0f * py;
    const float m2z = -2.0f * pz;

    float best[KNN];
#pragma unroll
    for (int t = 0; t < KNN; t++) best[t] = 3.4e38f;

    const int warp = threadIdx.x >> 5;
    const int sg0 = tile * 8 + warp;    // this warp's own supergroup first

#pragma unroll 1
    for (int ss = 0; ss < NSUPER; ss++) {
        const int s = (sg0 + ss) & (NSUPER - 1);

        const float lb32 = box_lb(px, py, pz, b32lo[s], b32hi[s]);
        if (!__any_sync(0xffffffffu, lb32 < best[KNN - 1])) continue;

#pragma unroll 1
        for (int u = 0; u < 4; u++) {
            const int gidx = s * 4 + u;

            const float lb8 = box_lb(px, py, pz, b8lo[gidx], b8hi[gidx]);
            if (!__any_sync(0xffffffffu, lb8 < best[KNN - 1])) continue;

            const int base = gidx << 3;
            float c[G];
#pragma unroll
            for (int v = 0; v < G; v++) {
                const float4 q = sm[base + v];   // LDS.128 broadcast
                c[v] = fmaf(q.x, m2x, fmaf(q.y, m2y, fmaf(q.z, m2z, si + q.w)));
            }

            const float m01 = fminf(c[0], c[1]);
            const float m23 = fminf(c[2], c[3]);
            const float m45 = fminf(c[4], c[5]);
            const float m67 = fminf(c[6], c[7]);
            const float m   = fminf(fminf(m01, m23), fminf(m45, m67));

            if (__any_sync(0xffffffffu, m < best[KNN - 1])) {
                // sort8 ascending (Batcher, 19 CE)
                CE(c[0], c[1]); CE(c[2], c[3]); CE(c[4], c[5]); CE(c[6], c[7]);
                CE(c[0], c[2]); CE(c[1], c[3]); CE(c[4], c[6]); CE(c[5], c[7]);
                CE(c[1], c[2]); CE(c[5], c[6]);
                CE(c[0], c[4]); CE(c[1], c[5]); CE(c[2], c[6]); CE(c[3], c[7]);
                CE(c[2], c[4]); CE(c[3], c[5]);
                CE(c[1], c[2]); CE(c[3], c[4]); CE(c[5], c[6]);

                // half-cleaner with best tail
                best[15] = fminf(best[15], c[0]);
                best[14] = fminf(best[14], c[1]);
                best[13] = fminf(best[13], c[2]);
                best[12] = fminf(best[12], c[3]);
                best[11] = fminf(best[11], c[4]);
                best[10] = fminf(best[10], c[5]);
                best[9]  = fminf(best[9],  c[6]);
                best[8]  = fminf(best[8],  c[7]);

                // bitonic merge16 ascending (32 CE)
#pragma unroll
                for (int t = 0; t < 8; t++)  CE(best[t], best[t + 8]);
#pragma unroll
                for (int h = 0; h < 16; h += 8)
#pragma unroll
                    for (int t = 0; t < 4; t++) CE(best[h + t], best[h + t + 4]);
#pragma unroll
                for (int h = 0; h < 16; h += 4)
#pragma unroll
                    for (int t = 0; t < 2; t++) CE(best[h + t], best[h + t + 2]);
#pragma unroll
                for (int h = 0; h < 16; h += 2)
                    CE(best[h], best[h + 1]);
            }
        }
    }

    float s = 0.0f;
#pragma unroll
    for (int t = 0; t < KNN; t++) s += best[t];
    s *= (1.0f / KNN);

#pragma unroll
    for (int off = 16; off > 0; off >>= 1)
        s += __shfl_down_sync(0xffffffffu, s, off);

    const int lid = threadIdx.x & 31;
    if (lid == 0) warp_sums[warp] = s;
    __syncthreads();

    if (threadIdx.x == 0) {
        float acc = 0.0f;
#pragma unroll
        for (int w = 0; w < TPB / 32; w++) acc += warp_sums[w];
        g_part[(z * NB + b) * TILES + tile] = acc;
        __threadfence();
        s_ticket = atomicAdd(&g_cnt, 1u);
    }
    __syncthreads();

    // Deterministic fixed-order finalize in the last block to arrive
    if (s_ticket == NBLOCKS - 1) {
        const int lane = threadIdx.x;
        if (lane < 32) {
            float val = 0.0f;
            if (lane < NB) {
                float S = 0.0f, Gv = 0.0f;
#pragma unroll
                for (int t = 0; t < TILES; t++) {
                    S  += g_part[(0 * NB + lane) * TILES + t];
                    Gv += g_part[(1 * NB + lane) * TILES + t];
                }
                const float d = (S - Gv) * (1.0f / (float)NPTS);
                val = d * d;
            }
#pragma unroll
            for (int off = 4; off > 0; off >>= 1)
                val += __shfl_down_sync(0xffffffffu, val, off);
            if (lane == 0) {
                out[0] = val * (1.0f / (float)NB);
                g_cnt = 0;   // self-reset for graph replay
            }
        }
    }
}

extern "C" void kernel_launch(void* const* d_in, const int* in_sizes, int n_in,
                              void* d_out, int out_size)
{
    const float* seed = (const float*)d_in[0];
    const float* gt_s = (const float*)d_in[1];
    float* out = (float*)d_out;

    dim3 sgrid(NB, 2);
    sort_kernel<<<sgrid, STPB>>>(seed, gt_s);

    dim3 grid(TILES, NB, 2);
    knn_kernel<<<grid, TPB>>>(out);
}

// round 9
// speedup vs baseline: 1.1764x; 1.1764x over previous
#include <cuda_runtime.h>
#include <cuda_bf16.h>

#define NPTS 2048
#define TPB  256
#define TILES (NPTS / TPB)   // 8
#define KNN  16
#define NB   8
#define G    8
#define NGROUPS (NPTS / G)   // 256
#define STPB 1024
#define NBLOCKS (TILES * NB * 2)   // 128

__device__ float g_part[2 * NB * TILES];
__device__ float4 g_sorted[2 * NB * NPTS];
__device__ unsigned g_cnt;

#define CE(a, b) { float _lo = fminf(a, b); float _hi = fmaxf(a, b); a = _lo; b = _hi; }

// sort8 + half-cleaner + bitonic merge16 (exact top-16 maintenance)
#define MERGE_GROUP(c, best) {                                              \
    CE(c[0], c[1]); CE(c[2], c[3]); CE(c[4], c[5]); CE(c[6], c[7]);         \
    CE(c[0], c[2]); CE(c[1], c[3]); CE(c[4], c[6]); CE(c[5], c[7]);         \
    CE(c[1], c[2]); CE(c[5], c[6]);                                         \
    CE(c[0], c[4]); CE(c[1], c[5]); CE(c[2], c[6]); CE(c[3], c[7]);         \
    CE(c[2], c[4]); CE(c[3], c[5]);                                         \
    CE(c[1], c[2]); CE(c[3], c[4]); CE(c[5], c[6]);                         \
    best[15] = fminf(best[15], c[0]);                                       \
    best[14] = fminf(best[14], c[1]);                                       \
    best[13] = fminf(best[13], c[2]);                                       \
    best[12] = fminf(best[12], c[3]);                                       \
    best[11] = fminf(best[11], c[4]);                                       \
    best[10] = fminf(best[10], c[5]);                                       \
    best[9]  = fminf(best[9],  c[6]);                                       \
    best[8]  = fminf(best[8],  c[7]);                                       \
    _Pragma("unroll")                                                       \
    for (int t = 0; t < 8; t++)  CE(best[t], best[t + 8]);                  \
    _Pragma("unroll")                                                       \
    for (int h = 0; h < 16; h += 8)                                         \
        for (int t = 0; t < 4; t++) CE(best[h + t], best[h + t + 4]);       \
    _Pragma("unroll")                                                       \
    for (int h = 0; h < 16; h += 4)                                         \
        for (int t = 0; t < 2; t++) CE(best[h + t], best[h + t + 2]);       \
    _Pragma("unroll")                                                       \
    for (int h = 0; h < 16; h += 2)                                         \
        CE(best[h], best[h + 1]);                                           \
}

__device__ __forceinline__ unsigned expand3(unsigned v) {
    v &= 0x3FFu;
    v = (v | (v << 16)) & 0x030000FFu;
    v = (v | (v << 8))  & 0x0300F00Fu;
    v = (v | (v << 4))  & 0x030C30C3u;
    v = (v | (v << 2))  & 0x09249249u;
    return v;
}

__global__ void __launch_bounds__(STPB, 1)
sort_kernel(const float* __restrict__ seed, const float* __restrict__ gt)
{
    __shared__ unsigned keys[NPTS];
    __shared__ float4 spts[NPTS];

    const int b = blockIdx.x;
    const int z = blockIdx.y;
    const float* pts = (z == 0 ? seed : gt) + (size_t)b * NPTS * 3;
    const int tid = threadIdx.x;

#pragma unroll
    for (int j = tid; j < NPTS; j += STPB) {
        const float x  = pts[3 * j + 0];
        const float y  = pts[3 * j + 1];
        const float zc = pts[3 * j + 2];
        spts[j] = make_float4(x, y, zc, fmaf(x, x, fmaf(y, y, zc * zc)));
        const unsigned qx = (unsigned)fminf(fmaxf((x  + 4.0f) * 16.0f, 0.0f), 127.0f);
        const unsigned qy = (unsigned)fminf(fmaxf((y  + 4.0f) * 16.0f, 0.0f), 127.0f);
        const unsigned qz = (unsigned)fminf(fmaxf((zc + 4.0f) * 16.0f, 0.0f), 127.0f);
        const unsigned code = (expand3(qx) << 2) | (expand3(qy) << 1) | expand3(qz);
        keys[j] = (code << 11) | (unsigned)j;   // unique -> deterministic
    }
    __syncthreads();

    for (unsigned k = 2; k <= NPTS; k <<= 1) {
        for (unsigned jj = k >> 1; jj > 0; jj >>= 1) {
            const unsigned t = (unsigned)tid;
            const unsigned i = ((t & ~(jj - 1u)) << 1) | (t & (jj - 1u));
            const unsigned pp = i | jj;
            const bool up = ((i & k) == 0u);
            const unsigned a  = keys[i];
            const unsigned c  = keys[pp];
            const unsigned lo = a < c ? a : c;
            const unsigned hi = a < c ? c : a;
            keys[i]  = up ? lo : hi;
            keys[pp] = up ? hi : lo;
            __syncthreads();
        }
    }

    float4* dst = g_sorted + (size_t)(z * NB + b) * NPTS;
#pragma unroll
    for (int idx = tid; idx < NPTS; idx += STPB)
        dst[idx] = spts[keys[idx] & 2047u];
}

__global__ void __launch_bounds__(TPB, 1)
knn_kernel(float* __restrict__ out)
{
    __shared__ float4 sm[NPTS];           // 32 KB
    __shared__ float warp_sums[TPB / 32];
    __shared__ unsigned s_ticket;

    const int tile = blockIdx.x;
    const int b    = blockIdx.y;
    const int z    = blockIdx.z;

    const float4* src = g_sorted + (size_t)(z * NB + b) * NPTS;
    for (int j = threadIdx.x; j < NPTS; j += TPB)
        sm[j] = src[j];
    __syncthreads();

    const int i = tile * TPB + threadIdx.x;
    const float4 p = sm[i];
    const float si  = p.w;
    const float m2x = -2.0f * p.x;
    const float m2y = -2.0f * p.y;
    const float m2z = -2.0f * p.z;

    float best[KNN];
#pragma unroll
    for (int t = 0; t < KNN; t++) best[t] = 3.4e38f;

    const int warp = threadIdx.x >> 5;
    const int g0 = (tile * TPB + warp * 32) >> 3;   // rotated start (own blob first)

#pragma unroll 1
    for (int gg = 0; gg < NGROUPS; gg += 2) {
        const int baseA = (((g0 + gg)     & (NGROUPS - 1)) << 3);
        const int baseB = (((g0 + gg + 1) & (NGROUPS - 1)) << 3);

        // Two fully independent chains: loads, distances, min-trees, votes.
        float a[G], c[G];
#pragma unroll
        for (int u = 0; u < G; u++) {
            const float4 qa = sm[baseA + u];
            a[u] = fmaf(qa.x, m2x, fmaf(qa.y, m2y, fmaf(qa.z, m2z, si + qa.w)));
        }
#pragma unroll
        for (int u = 0; u < G; u++) {
            const float4 qb = sm[baseB + u];
            c[u] = fmaf(qb.x, m2x, fmaf(qb.y, m2y, fmaf(qb.z, m2z, si + qb.w)));
        }

        const float ma = fminf(fminf(fminf(a[0], a[1]), fminf(a[2], a[3])),
                               fminf(fminf(a[4], a[5]), fminf(a[6], a[7])));
        const float mb = fminf(fminf(fminf(c[0], c[1]), fminf(c[2], c[3])),
                               fminf(fminf(c[4], c[5]), fminf(c[6], c[7])));

        const float thr = best[KNN - 1];
        const bool enterA = __any_sync(0xffffffffu, ma < thr);
        const bool enterB = __any_sync(0xffffffffu, mb < thr);

        if (enterA) { MERGE_GROUP(a, best); }
        if (enterB) {
            // Re-check B against the tightened threshold is NOT needed for
            // correctness (merge is exact), just run it.
            MERGE_GROUP(c, best);
        }
    }

    float s = 0.0f;
#pragma unroll
    for (int t = 0; t < KNN; t++) s += best[t];
    s *= (1.0f / KNN);

#pragma unroll
    for (int off = 16; off > 0; off >>= 1)
        s += __shfl_down_sync(0xffffffffu, s, off);

    const int lid = threadIdx.x & 31;
    if (lid == 0) warp_sums[warp] = s;
    __syncthreads();

    if (threadIdx.x == 0) {
        float acc = 0.0f;
#pragma unroll
        for (int w = 0; w < TPB / 32; w++) acc += warp_sums[w];
        g_part[(z * NB + b) * TILES + tile] = acc;
        __threadfence();
        s_ticket = atomicAdd(&g_cnt, 1u);
    }
    __syncthreads();

    // Deterministic fixed-order finalize in the last block to arrive
    if (s_ticket == NBLOCKS - 1) {
        const int lane = threadIdx.x;
        if (lane < 32) {
            float val = 0.0f;
            if (lane < NB) {
                float S = 0.0f, Gv = 0.0f;
#pragma unroll
                for (int t = 0; t < TILES; t++) {
                    S  += g_part[(0 * NB + lane) * TILES + t];
                    Gv += g_part[(1 * NB + lane) * TILES + t];
                }
                const float d = (S - Gv) * (1.0f / (float)NPTS);
                val = d * d;
            }
#pragma unroll
            for (int off = 4; off > 0; off >>= 1)
                val += __shfl_down_sync(0xffffffffu, val, off);
            if (lane == 0) {
                out[0] = val * (1.0f / (float)NB);
                g_cnt = 0;   // self-reset for graph replay
            }
        }
    }
}

extern "C" void kernel_launch(void* const* d_in, const int* in_sizes, int n_in,
                              void* d_out, int out_size)
{
    const float* seed = (const float*)d_in[0];
    const float* gt_s = (const float*)d_in[1];
    float* out = (float*)d_out;

    dim3 sgrid(NB, 2);
    sort_kernel<<<sgrid, STPB>>>(seed, gt_s);

    dim3 grid(TILES, NB, 2);
    knn_kernel<<<grid, TPB>>>(out);
}

// round 10
// speedup vs baseline: 1.2147x; 1.0326x over previous
#include <cuda_runtime.h>
#include <cuda_bf16.h>

#define NPTS 2048
#define TPB  256
#define TILES (NPTS / TPB)   // 8
#define KNN  16
#define NB   8
#define G    8
#define NGROUPS (NPTS / G)   // 256
#define STPB 1024
#define NBLOCKS (TILES * NB * 2)   // 128
#define NWIN (NPTS / 32)     // 64 sort windows
#define NWARPS_S (STPB / 32) // 32

__device__ float g_part[2 * NB * TILES];
__device__ float4 g_sorted[2 * NB * NPTS];
__device__ unsigned g_cnt;

#define CE(a, b) { float _lo = fminf(a, b); float _hi = fmaxf(a, b); a = _lo; b = _hi; }

// sort8 + half-cleaner + bitonic merge16 (exact top-16 maintenance)
#define MERGE_GROUP(c, best) {                                              \
    CE(c[0], c[1]); CE(c[2], c[3]); CE(c[4], c[5]); CE(c[6], c[7]);         \
    CE(c[0], c[2]); CE(c[1], c[3]); CE(c[4], c[6]); CE(c[5], c[7]);         \
    CE(c[1], c[2]); CE(c[5], c[6]);                                         \
    CE(c[0], c[4]); CE(c[1], c[5]); CE(c[2], c[6]); CE(c[3], c[7]);         \
    CE(c[2], c[4]); CE(c[3], c[5]);                                         \
    CE(c[1], c[2]); CE(c[3], c[4]); CE(c[5], c[6]);                         \
    best[15] = fminf(best[15], c[0]);                                       \
    best[14] = fminf(best[14], c[1]);                                       \
    best[13] = fminf(best[13], c[2]);                                       \
    best[12] = fminf(best[12], c[3]);                                       \
    best[11] = fminf(best[11], c[4]);                                       \
    best[10] = fminf(best[10], c[5]);                                       \
    best[9]  = fminf(best[9],  c[6]);                                       \
    best[8]  = fminf(best[8],  c[7]);                                       \
    _Pragma("unroll")                                                       \
    for (int t = 0; t < 8; t++)  CE(best[t], best[t + 8]);                  \
    _Pragma("unroll")                                                       \
    for (int h = 0; h < 16; h += 8)                                         \
        for (int t = 0; t < 4; t++) CE(best[h + t], best[h + t + 4]);       \
    _Pragma("unroll")                                                       \
    for (int h = 0; h < 16; h += 4)                                         \
        for (int t = 0; t < 2; t++) CE(best[h + t], best[h + t + 2]);       \
    _Pragma("unroll")                                                       \
    for (int h = 0; h < 16; h += 2)                                         \
        CE(best[h], best[h + 1]);                                           \
}

#define DIST8(arr, base) {                                                  \
    _Pragma("unroll")                                                       \
    for (int u = 0; u < G; u++) {                                           \
        const float4 q = sm[(base) + u];                                    \
        arr[u] = fmaf(q.x, m2x, fmaf(q.y, m2y, fmaf(q.z, m2z, si + q.w)));  \
    }                                                                       \
}

#define MIN8(arr) fminf(fminf(fminf(arr[0], arr[1]), fminf(arr[2], arr[3])),\
                        fminf(fminf(arr[4], arr[5]), fminf(arr[6], arr[7])))

__device__ __forceinline__ unsigned expand3(unsigned v) {
    v &= 0x3FFu;
    v = (v | (v << 16)) & 0x030000FFu;
    v = (v | (v << 8))  & 0x0300F00Fu;
    v = (v | (v << 4))  & 0x030C30C3u;
    v = (v | (v << 2))  & 0x09249249u;
    return v;
}

__global__ void __launch_bounds__(STPB, 1)
sort_kernel(const float* __restrict__ seed, const float* __restrict__ gt)
{
    __shared__ unsigned keys[NPTS];
    __shared__ float4 spts[NPTS];

    const int b = blockIdx.x;
    const int z = blockIdx.y;
    const float* pts = (z == 0 ? seed : gt) + (size_t)b * NPTS * 3;
    const int tid  = threadIdx.x;
    const int warp = tid >> 5;
    const int lane = tid & 31;

#pragma unroll
    for (int j = tid; j < NPTS; j += STPB) {
        const float x  = pts[3 * j + 0];
        const float y  = pts[3 * j + 1];
        const float zc = pts[3 * j + 2];
        spts[j] = make_float4(x, y, zc, fmaf(x, x, fmaf(y, y, zc * zc)));
        const unsigned qx = (unsigned)fminf(fmaxf((x  + 4.0f) * 16.0f, 0.0f), 127.0f);
        const unsigned qy = (unsigned)fminf(fmaxf((y  + 4.0f) * 16.0f, 0.0f), 127.0f);
        const unsigned qz = (unsigned)fminf(fmaxf((zc + 4.0f) * 16.0f, 0.0f), 127.0f);
        const unsigned code = (expand3(qx) << 2) | (expand3(qy) << 1) | expand3(qz);
        keys[j] = (code << 11) | (unsigned)j;   // unique -> deterministic
    }
    __syncthreads();

    // ---- k = 2..32 entirely in registers (15 phases, no barriers inside) ----
#pragma unroll
    for (int w = warp; w < NWIN; w += NWARPS_S) {
        unsigned v = keys[w * 32 + lane];
#pragma unroll
        for (unsigned k = 2; k <= 16; k <<= 1) {
#pragma unroll
            for (unsigned j = k >> 1; j > 0; j >>= 1) {
                const unsigned o = __shfl_xor_sync(0xffffffffu, v, j);
                const bool up    = ((lane & k) == 0u);
                const bool lower = ((lane & j) == 0u);
                v = (lower == up) ? (v < o ? v : o) : (v > o ? v : o);
            }
        }
        {   // k = 32: direction uniform per window
            const bool up = ((w & 1) == 0);
#pragma unroll
            for (unsigned j = 16; j > 0; j >>= 1) {
                const unsigned o = __shfl_xor_sync(0xffffffffu, v, j);
                const bool lower = ((lane & j) == 0u);
                v = (lower == up) ? (v < o ? v : o) : (v > o ? v : o);
            }
        }
        keys[w * 32 + lane] = v;
    }
    __syncthreads();

    // ---- k = 64..2048: smem phases for j>=32, register phases for j<=16 ----
    for (unsigned k = 64; k <= NPTS; k <<= 1) {
        for (unsigned jj = k >> 1; jj >= 32; jj >>= 1) {
            const unsigned t = (unsigned)tid;
            const unsigned i = ((t & ~(jj - 1u)) << 1) | (t & (jj - 1u));
            const unsigned pp = i | jj;
            const bool up = ((i & k) == 0u);
            const unsigned a  = keys[i];
            const unsigned c  = keys[pp];
            const unsigned lo = a < c ? a : c;
            const unsigned hi = a < c ? c : a;
            keys[i]  = up ? lo : hi;
            keys[pp] = up ? hi : lo;
            __syncthreads();
        }
#pragma unroll
        for (int w = warp; w < NWIN; w += NWARPS_S) {
            unsigned v = keys[w * 32 + lane];
            const bool up = (((unsigned)(w * 32) & k) == 0u);
#pragma unroll
            for (unsigned j = 16; j > 0; j >>= 1) {
                const unsigned o = __shfl_xor_sync(0xffffffffu, v, j);
                const bool lower = ((lane & j) == 0u);
                v = (lower == up) ? (v < o ? v : o) : (v > o ? v : o);
            }
            keys[w * 32 + lane] = v;
        }
        __syncthreads();
    }

    float4* dst = g_sorted + (size_t)(z * NB + b) * NPTS;
#pragma unroll
    for (int idx = tid; idx < NPTS; idx += STPB)
        dst[idx] = spts[keys[idx] & 2047u];
}

__global__ void __launch_bounds__(TPB, 1)
knn_kernel(float* __restrict__ out)
{
    __shared__ float4 sm[NPTS];           // 32 KB
    __shared__ float warp_sums[TPB / 32];
    __shared__ unsigned s_ticket;

    const int tile = blockIdx.x;
    const int b    = blockIdx.y;
    const int z    = blockIdx.z;

    const float4* src = g_sorted + (size_t)(z * NB + b) * NPTS;
    for (int j = threadIdx.x; j < NPTS; j += TPB)
        sm[j] = src[j];
    __syncthreads();

    const int i = tile * TPB + threadIdx.x;
    const float4 p = sm[i];
    const float si  = p.w;
    const float m2x = -2.0f * p.x;
    const float m2y = -2.0f * p.y;
    const float m2z = -2.0f * p.z;

    float best[KNN];
#pragma unroll
    for (int t = 0; t < KNN; t++) best[t] = 3.4e38f;

    const int warp = threadIdx.x >> 5;
    const int g0 = (tile * TPB + warp * 32) >> 3;   // rotated start (own blob first)

#pragma unroll 1
    for (int gg = 0; gg < NGROUPS; gg += 4) {
        const int baseA = (((g0 + gg)     & (NGROUPS - 1)) << 3);
        const int baseB = (((g0 + gg + 1) & (NGROUPS - 1)) << 3);
        const int baseC = (((g0 + gg + 2) & (NGROUPS - 1)) << 3);
        const int baseD = (((g0 + gg + 3) & (NGROUPS - 1)) << 3);

        // Four fully independent chains: loads, distances, min-trees, votes.
        float a[G], c[G], d[G], e[G];
        DIST8(a, baseA);
        DIST8(c, baseB);
        DIST8(d, baseC);
        DIST8(e, baseD);

        const float ma = MIN8(a);
        const float mb = MIN8(c);
        const float mc = MIN8(d);
        const float md = MIN8(e);

        const float thr = best[KNN - 1];
        const bool enterA = __any_sync(0xffffffffu, ma < thr);
        const bool enterB = __any_sync(0xffffffffu, mb < thr);
        const bool enterC = __any_sync(0xffffffffu, mc < thr);
        const bool enterD = __any_sync(0xffffffffu, md < thr);

        if (enterA) { MERGE_GROUP(a, best); }
        if (enterB) { MERGE_GROUP(c, best); }
        if (enterC) { MERGE_GROUP(d, best); }
        if (enterD) { MERGE_GROUP(e, best); }
    }

    float s = 0.0f;
#pragma unroll
    for (int t = 0; t < KNN; t++) s += best[t];
    s *= (1.0f / KNN);

#pragma unroll
    for (int off = 16; off > 0; off >>= 1)
        s += __shfl_down_sync(0xffffffffu, s, off);

    const int lid = threadIdx.x & 31;
    if (lid == 0) warp_sums[warp] = s;
    __syncthreads();

    if (threadIdx.x == 0) {
        float acc = 0.0f;
#pragma unroll
        for (int w = 0; w < TPB / 32; w++) acc += warp_sums[w];
        g_part[(z * NB + b) * TILES + tile] = acc;
        __threadfence();
        s_ticket = atomicAdd(&g_cnt, 1u);
    }
    __syncthreads();

    // Deterministic fixed-order finalize in the last block to arrive
    if (s_ticket == NBLOCKS - 1) {
        const int lane = threadIdx.x;
        if (lane < 32) {
            float val = 0.0f;
            if (lane < NB) {
                float S = 0.0f, Gv = 0.0f;
#pragma unroll
                for (int t = 0; t < TILES; t++) {
                    S  += g_part[(0 * NB + lane) * TILES + t];
                    Gv += g_part[(1 * NB + lane) * TILES + t];
                }
                const float dd = (S - Gv) * (1.0f / (float)NPTS);
                val = dd * dd;
            }
#pragma unroll
            for (int off = 4; off > 0; off >>= 1)
                val += __shfl_down_sync(0xffffffffu, val, off);
            if (lane == 0) {
                out[0] = val * (1.0f / (float)NB);
                g_cnt = 0;   // self-reset for graph replay
            }
        }
    }
}

extern "C" void kernel_launch(void* const* d_in, const int* in_sizes, int n_in,
                              void* d_out, int out_size)
{
    const float* seed = (const float*)d_in[0];
    const float* gt_s = (const float*)d_in[1];
    float* out = (float*)d_out;

    dim3 sgrid(NB, 2);
    sort_kernel<<<sgrid, STPB>>>(seed, gt_s);

    dim3 grid(TILES, NB, 2);
    knn_kernel<<<grid, TPB>>>(out);
}